// round 4
// baseline (speedup 1.0000x reference)
#include <cuda_runtime.h>
#include <cuda_bf16.h>

// Cumulative mean over axis 0 of x[8192, 4096] fp32:
//   out[r, c] = (sum_{i<=r} x[i, c]) / (r + 1)
//
// Single-pass decoupled-lookback scan, tile register-resident (x read ONCE).
//   TPB = 256 threads, each thread owns one float4 column (16 B).
//   Tile = 16 rows x 1024 columns; NCB = 4 column blocks; NTILES = 512.
//   Grid = 2048 blocks, row-tile-major: predecessors have lower blockIdx.
//   Flags: 0 = none, 1 = aggregate ready, 2 = inclusive prefix ready.

#define ROWS   8192
#define COLS   4096
#define T      16
#define NTILES (ROWS / T)            // 512
#define TPB    256
#define CB_W   (TPB * 4)             // 1024 columns per block
#define NCB    (COLS / CB_W)         // 4
#define C4     (COLS / 4)            // 1024 float4 per row

// Static device scratch (no allocation allowed anywhere).
__device__ float4 g_agg[NCB * NTILES * TPB];   // 8 MB: per-tile per-thread sums
__device__ float4 g_inc[NCB * NTILES * TPB];   // 8 MB: per-tile per-thread inclusive prefix
__device__ int    g_flag[NCB * NTILES];        // 8 KB
__device__ float  g_inv[ROWS];                 // 32 KB: 1/(r+1)

__device__ __forceinline__ float4 f4_add(float4 a, float4 b) {
    a.x += b.x; a.y += b.y; a.z += b.z; a.w += b.w;
    return a;
}

__global__ void k_init() {
    int i = blockIdx.x * blockDim.x + threadIdx.x;
    if (i < ROWS) g_inv[i] = 1.0f / (float)(i + 1);
    if (i < NCB * NTILES) g_flag[i] = 0;
}

__global__ void __launch_bounds__(TPB)
k_scan(const float* __restrict__ x, float* __restrict__ out) {
    const int bx  = blockIdx.x;
    const int rt  = bx / NCB;              // row tile (low tiles dispatch first)
    const int cb  = bx % NCB;              // column block
    const int tid = threadIdx.x;

    const float4* __restrict__ x4 = reinterpret_cast<const float4*>(x);
    float4*       __restrict__ o4 = reinterpret_cast<float4*>(out);

    const int col4 = cb * TPB + tid;       // this thread's float4 column
    const int base = rt * T * C4 + col4;

    // ---- Phase 1: load tile into registers, compute aggregate --------------
    float4 v[T];
#pragma unroll
    for (int r = 0; r < T; r++) v[r] = __ldg(&x4[base + r * C4]);

    float4 agg = v[0];
#pragma unroll
    for (int r = 1; r < T; r++) agg = f4_add(agg, v[r]);

    const int sidx = cb * NTILES + rt;
    g_agg[(size_t)sidx * TPB + tid] = agg;
    __syncthreads();                       // all payload stores done (block scope)
    if (tid == 0) {
        __threadfence();                   // cumulative release to GPU scope
        atomicExch(&g_flag[sidx], 1);
    }

    // ---- Decoupled lookback ------------------------------------------------
    float4 prefix = make_float4(0.f, 0.f, 0.f, 0.f);
    __shared__ int s_flag;
    for (int p = rt - 1; p >= 0; p--) {
        const int fidx = cb * NTILES + p;
        if (tid == 0) {
            int f = atomicOr(&g_flag[fidx], 0);
            while (f == 0) {
                __nanosleep(64);
                f = atomicOr(&g_flag[fidx], 0);
            }
            __threadfence();               // acquire: order payload reads after flag
            s_flag = f;
        }
        __syncthreads();
        const int f = s_flag;
        float4 pv;
        if (f == 2) pv = __ldcg(&g_inc[(size_t)fidx * TPB + tid]);
        else        pv = __ldcg(&g_agg[(size_t)fidx * TPB + tid]);
        prefix = f4_add(prefix, pv);
        __syncthreads();                   // protect s_flag for next iteration
        if (f == 2) break;
    }

    // ---- Publish inclusive prefix ASAP (before stores) ---------------------
    g_inc[(size_t)sidx * TPB + tid] = f4_add(prefix, agg);
    __syncthreads();
    if (tid == 0) {
        __threadfence();
        atomicExch(&g_flag[sidx], 2);
    }

    // ---- Phase 2: scan registers, scale, store (no re-read) ----------------
    float4 run = prefix;
#pragma unroll
    for (int r = 0; r < T; r++) {
        run = f4_add(run, v[r]);
        const float inv = __ldg(&g_inv[rt * T + r]);   // warp-uniform, L1-hit
        float4 o;
        o.x = run.x * inv; o.y = run.y * inv;
        o.z = run.z * inv; o.w = run.w * inv;
        o4[base + r * C4] = o;
    }
}

extern "C" void kernel_launch(void* const* d_in, const int* in_sizes, int n_in,
                              void* d_out, int out_size) {
    const float* x   = (const float*)d_in[0];
    float*       out = (float*)d_out;

    k_init<<<(ROWS + 255) / 256, 256>>>();
    k_scan<<<NTILES * NCB, TPB>>>(x, out);
}